// round 5
// baseline (speedup 1.0000x reference)
#include <cuda_runtime.h>
#include <stdint.h>

// Problem constants
constexpr int Fdim = 64;
constexpr int Rdim = 1024;
constexpr int Pdim = 128;
constexpr int BM   = 128;           // batch rows per CTA
constexpr int NCR  = 256;           // rules per chunk
constexpr int NCH  = Rdim / NCR;    // 4 chunks
constexpr int K8   = 33;            // k8 tiles (K padded to 264)
constexpr int QK8  = 3;             // k8 tiles per quarter-step
constexpr int NQ   = 11;            // quarter-steps per chunk
constexpr int NSTEP = NCH * NQ;     // 44
constexpr int NTH  = 512;           // 16 warps
constexpr int NT   = 8;             // n8-tiles per warp (64 rules)
constexpr int STEP_FLOATS = 4 * QK8 * 32 * NT * 2;   // 6144
constexpr int STEP_BYTES  = STEP_FLOATS * 4;         // 24576

#define LOG2E 1.4426950408889634f

// ---- Device-global scratch ----
__device__ uint32_t g_Bf[NSTEP * STEP_FLOATS];  // B in mma-fragment order, tf32
__device__ float4   g_kc[Rdim];                 // -pp*sign*log2e
__device__ float4   g_cc[Rdim];                 //  pp*sign*th*log2e
__device__ float4   g_mm[Rdim];                 //  mask

__device__ __forceinline__ float ex2f(float x) {
    float y; asm("ex2.approx.f32 %0, %1;" : "=f"(y) : "f"(x)); return y;
}
__device__ __forceinline__ float rcpf(float x) {
    float y; asm("rcp.approx.f32 %0, %1;" : "=f"(y) : "f"(x)); return y;
}
__device__ __forceinline__ uint32_t to_tf32(float f) {
    uint32_t r; asm("cvt.rna.tf32.f32 %0, %1;" : "=r"(r) : "f"(f)); return r;
}

// A fragment slot (float index) for logical element (row, k).
__device__ __forceinline__ int afrag_idx(int row, int k) {
    int m = row >> 4, g = row & 7, hi = (row >> 3) & 1;
    int k8 = k >> 3, tig = k & 3, khi = (k >> 2) & 1;
    return ((m * K8 + k8) * 32 + g * 4 + tig) * 4 + (hi + 2 * khi);
}

__global__ void prep_kernel(const float* __restrict__ C,    // [R][257]
                            const float* __restrict__ pp,   // [R]
                            const float* __restrict__ th,   // [R][4]
                            const float* __restrict__ sg,   // [R][4]
                            const float* __restrict__ mk)   // [R][4]
{
    int t = blockIdx.x * blockDim.x + threadIdx.x;
    // B layout per step: [wc(4)][k8q(3)][lane(32)][nt(8)][2 regs]
    if (t < Rdim * K8) {
        int r  = t / K8;
        int k8 = t - r * K8;
        int chunk = r >> 8, rl = r & 255;
        int wc = rl >> 6;
        int nt = (rl >> 3) & 7;
        int nn = rl & 7;
        int q = k8 / QK8, k8q = k8 - q * QK8;
        size_t stepBase = (size_t)(chunk * NQ + q) * STEP_FLOATS;
        #pragma unroll
        for (int tig = 0; tig < 4; tig++) {
            int kk0 = k8 * 8 + tig;
            int kk1 = k8 * 8 + 4 + tig;
            uint32_t v0 = (kk0 < 257) ? to_tf32(C[r * 257 + kk0]) : 0u;
            uint32_t v1 = (kk1 < 257) ? to_tf32(C[r * 257 + kk1]) : 0u;
            size_t idx = stepBase +
                (size_t)((((wc * QK8 + k8q) * 32 + nn * 4 + tig) * NT + nt) * 2);
            *(uint2*)&g_Bf[idx] = make_uint2(v0, v1);
        }
    }
    if (t < Rdim) {
        float s = pp[t];
        float kc[4], cc[4], mm[4];
        #pragma unroll
        for (int l = 0; l < 4; l++) {
            float sgn = sg[t * 4 + l];
            float tt  = th[t * 4 + l];
            kc[l] = -s * sgn * LOG2E;
            cc[l] =  s * sgn * tt * LOG2E;
            mm[l] = mk[t * 4 + l];
        }
        g_kc[t] = make_float4(kc[0], kc[1], kc[2], kc[3]);
        g_cc[t] = make_float4(cc[0], cc[1], cc[2], cc[3]);
        g_mm[t] = make_float4(mm[0], mm[1], mm[2], mm[3]);
    }
}

// ---- Shared memory layout (bytes) ----
constexpr int SMA  = 0;                       // A frags: 33792 u32 = 135168 B
constexpr int SMB  = 135168;                  // B double buffer: 2*24576 = 49152 B
constexpr int SMXA = 184320;                  // sXa: 64 x 132 f32 = 33792 B
constexpr int SMEM_BYTES = 218112;

__global__ __launch_bounds__(NTH, 1)
void anfis_kernel(const float* __restrict__ x,        // [B][64]
                  const float* __restrict__ aw,       // [64]
                  const int*   __restrict__ fidx,     // [R][4]
                  const int*   __restrict__ ipair,    // [P][2]
                  float*       __restrict__ out)      // [B]
{
    extern __shared__ char smem[];
    const int tid  = threadIdx.x;
    const int wid  = tid >> 5;
    const int lane = tid & 31;
    const int g    = lane >> 2;
    const int tig  = lane & 3;
    const int wr   = wid >> 2;   // 0..3 : row group (32 rows)
    const int wc   = wid & 3;    // 0..3 : rule group (64 rules)
    const int b0   = blockIdx.x * BM;

    uint32_t* sA  = (uint32_t*)smem;
    float*    sXa = (float*)(smem + SMXA);
    const uint32_t smu  = (uint32_t)__cvta_generic_to_shared(smem);
    const uint32_t smAu = smu + SMA;
    const uint32_t smBu = smu + SMB;

    // ---- Prologue: build A fragments (tf32) + sXa (f32) ----
    #pragma unroll
    for (int pass = 0; pass < 4; pass++) {
        int idx = tid + pass * NTH;     // 0..2047
        int b = idx >> 4;
        int q = idx & 15;
        int f = q * 4;
        float4 xv = *(const float4*)&x[(b0 + b) * Fdim + f];
        float4 av = __ldg((const float4*)aw + q);
        float xa[4] = {xv.x * av.x, xv.y * av.y, xv.z * av.z, xv.w * av.w};
        #pragma unroll
        for (int j = 0; j < 4; j++) {
            sA[afrag_idx(b, f + j)]      = to_tf32(xa[j]);
            sA[afrag_idx(b, 64 + f + j)] = to_tf32(xa[j] * xa[j]);
            sXa[(f + j) * 132 + b] = xa[j];
        }
    }
    __syncthreads();
    {
        int b  = tid & 127;
        int pg = tid >> 7;              // 0..3
        for (int pi = pg; pi < Pdim; pi += 4) {
            int2 pr = __ldg((const int2*)ipair + pi);
            float v = sXa[pr.x * 132 + b] * sXa[pr.y * 132 + b];
            sA[afrag_idx(b, 128 + pi)] = to_tf32(v);
        }
        if (pg == 0) {
            sA[afrag_idx(b, 256)] = to_tf32(1.0f);
            #pragma unroll
            for (int k = 257; k < 264; k++) sA[afrag_idx(b, k)] = 0u;
        }
    }
    __syncthreads();

    // ---- B streamer (all threads): one step = 24576 B ----
    auto issue = [&](int step) {
        const char* src = (const char*)g_Bf + (size_t)step * STEP_BYTES;
        uint32_t dst = smBu + (uint32_t)(step & 1) * STEP_BYTES;
        #pragma unroll
        for (int i = 0; i < 3; i++) {
            asm volatile("cp.async.cg.shared.global [%0], [%1], 16;"
                         :: "r"(dst + (tid + i * NTH) * 16),
                            "l"(src + (tid + i * NTH) * 16) : "memory");
        }
        asm volatile("cp.async.commit_group;" ::: "memory");
    };

    float accY[4] = {0.f, 0.f, 0.f, 0.f};
    float accS[4] = {0.f, 0.f, 0.f, 0.f};

    issue(0);

    for (int chunk = 0; chunk < NCH; chunk++) {
        float d[2][NT][4];
        #pragma unroll
        for (int mi = 0; mi < 2; mi++)
            #pragma unroll
            for (int nt = 0; nt < NT; nt++)
                #pragma unroll
                for (int rr = 0; rr < 4; rr++) d[mi][nt][rr] = 0.f;

        for (int qq = 0; qq < NQ; qq++) {
            int step = chunk * NQ + qq;
            if (step + 1 < NSTEP) {
                issue(step + 1);
                asm volatile("cp.async.wait_group 1;" ::: "memory");
            } else {
                asm volatile("cp.async.wait_group 0;" ::: "memory");
            }
            __syncthreads();

            uint32_t bufb = smBu + (uint32_t)(step & 1) * STEP_BYTES;

            #pragma unroll
            for (int k8q = 0; k8q < QK8; k8q++) {
                int k8 = qq * QK8 + k8q;
                uint32_t a[2][4];
                #pragma unroll
                for (int mi = 0; mi < 2; mi++) {
                    uint32_t aAddr = smAu +
                        (uint32_t)((((wr * 2 + mi) * K8 + k8) * 32 + lane) * 16);
                    asm("ld.shared.v4.b32 {%0,%1,%2,%3}, [%4];"
                        : "=r"(a[mi][0]), "=r"(a[mi][1]),
                          "=r"(a[mi][2]), "=r"(a[mi][3]) : "r"(aAddr));
                }
                uint32_t bfr[NT][2];
                #pragma unroll
                for (int p = 0; p < NT / 2; p++) {
                    uint32_t bAddr = bufb +
                        (uint32_t)(((wc * QK8 + k8q) * 32 + lane) * (NT * 8) + p * 16);
                    asm("ld.shared.v4.b32 {%0,%1,%2,%3}, [%4];"
                        : "=r"(bfr[2 * p][0]), "=r"(bfr[2 * p][1]),
                          "=r"(bfr[2 * p + 1][0]), "=r"(bfr[2 * p + 1][1])
                        : "r"(bAddr));
                }
                #pragma unroll
                for (int mi = 0; mi < 2; mi++)
                    #pragma unroll
                    for (int nt = 0; nt < NT; nt++) {
                        asm("mma.sync.aligned.m16n8k8.row.col.f32.tf32.tf32.f32 "
                            "{%0,%1,%2,%3}, {%4,%5,%6,%7}, {%8,%9}, {%0,%1,%2,%3};"
                            : "+f"(d[mi][nt][0]), "+f"(d[mi][nt][1]),
                              "+f"(d[mi][nt][2]), "+f"(d[mi][nt][3])
                            : "r"(a[mi][0]), "r"(a[mi][1]),
                              "r"(a[mi][2]), "r"(a[mi][3]),
                              "r"(bfr[nt][0]), "r"(bfr[nt][1]));
                    }
            }
            __syncthreads();
        }

        // ---- Fused epilogue: firing = 1 / prod(1 + m*exp(-z)) ----
        #pragma unroll
        for (int nt = 0; nt < NT; nt++) {
            #pragma unroll
            for (int ccc = 0; ccc < 2; ccc++) {
                int r = chunk * NCR + wc * 64 + nt * 8 + tig * 2 + ccc;
                float4 kc = __ldg(&g_kc[r]);
                float4 cc = __ldg(&g_cc[r]);
                float4 mm = __ldg(&g_mm[r]);
                int4   id = __ldg((const int4*)fidx + r);
                const float* x0 = sXa + id.x * 132;
                const float* x1 = sXa + id.y * 132;
                const float* x2 = sXa + id.z * 132;
                const float* x3 = sXa + id.w * 132;
                #pragma unroll
                for (int mi = 0; mi < 2; mi++) {
                    #pragma unroll
                    for (int hi = 0; hi < 2; hi++) {
                        int row = wr * 32 + mi * 16 + hi * 8 + g;
                        float u0 = ex2f(fmaf(kc.x, x0[row], cc.x));
                        float u1 = ex2f(fmaf(kc.y, x1[row], cc.y));
                        float u2 = ex2f(fmaf(kc.z, x2[row], cc.z));
                        float u3 = ex2f(fmaf(kc.w, x3[row], cc.w));
                        float fac = fmaf(mm.x, u0, 1.0f) * fmaf(mm.y, u1, 1.0f)
                                  * fmaf(mm.z, u2, 1.0f) * fmaf(mm.w, u3, 1.0f);
                        float f = rcpf(fac);
                        accS[mi * 2 + hi] += f;
                        accY[mi * 2 + hi] =
                            fmaf(f, d[mi][nt][hi * 2 + ccc], accY[mi * 2 + hi]);
                    }
                }
            }
        }
    }

    // ---- Reduce: shuffle over tig (4 lanes), then smem over wc (4 warps) ----
    #pragma unroll
    for (int s = 1; s <= 2; s <<= 1) {
        #pragma unroll
        for (int i = 0; i < 4; i++) {
            accY[i] += __shfl_xor_sync(0xffffffff, accY[i], s);
            accS[i] += __shfl_xor_sync(0xffffffff, accS[i], s);
        }
    }
    __syncthreads();
    float* redY = (float*)(smem + SMB);        // [128][4]
    float* redS = redY + 512;
    if (tig == 0) {
        #pragma unroll
        for (int i = 0; i < 4; i++) {
            int row = wr * 32 + (i >> 1) * 16 + (i & 1) * 8 + g;
            redY[row * 4 + wc] = accY[i];
            redS[row * 4 + wc] = accS[i];
        }
    }
    __syncthreads();
    if (tid < BM) {
        float sy = redY[tid * 4] + redY[tid * 4 + 1]
                 + redY[tid * 4 + 2] + redY[tid * 4 + 3];
        float ss = redS[tid * 4] + redS[tid * 4 + 1]
                 + redS[tid * 4 + 2] + redS[tid * 4 + 3];
        out[b0 + tid] = sy / (ss + 1e-8f);
    }
}

extern "C" void kernel_launch(void* const* d_in, const int* in_sizes, int n_in,
                              void* d_out, int out_size)
{
    const float* x    = (const float*)d_in[0];   // [16384,64]
    const float* aw   = (const float*)d_in[1];   // [64]
    const float* pp   = (const float*)d_in[2];   // [1024]
    const float* th   = (const float*)d_in[3];   // [1024,4]
    const float* sg   = (const float*)d_in[4];   // [1024,4]
    const float* mk   = (const float*)d_in[5];   // [1024,4]
    const float* C    = (const float*)d_in[6];   // [1024,257]
    const int*   fid  = (const int*)  d_in[7];   // [1024,4]
    const int*   ip   = (const int*)  d_in[8];   // [128,2]
    float* out = (float*)d_out;

    cudaFuncSetAttribute(anfis_kernel,
                         cudaFuncAttributeMaxDynamicSharedMemorySize,
                         SMEM_BYTES);

    prep_kernel<<<132, 256>>>(C, pp, th, sg, mk);
    anfis_kernel<<<16384 / BM, NTH, SMEM_BYTES>>>(x, aw, fid, ip, out);
}

// round 6
// speedup vs baseline: 1.4157x; 1.4157x over previous
#include <cuda_runtime.h>
#include <stdint.h>

// Problem constants
constexpr int Fdim = 64;
constexpr int Rdim = 1024;
constexpr int Pdim = 128;
constexpr int BM   = 128;           // batch rows per CTA
constexpr int NCR  = 256;           // rules per chunk
constexpr int NCH  = Rdim / NCR;    // 4 chunks
constexpr int K8   = 33;            // k8 tiles (K padded to 264)
constexpr int QK8  = 3;             // k8 tiles per step
constexpr int NQ   = 11;            // steps per chunk
constexpr int NSTEP = NCH * NQ;     // 44
constexpr int NTH  = 256;           // 8 warps (RF sweet spot: ~218 regs/thr)
constexpr int NT   = 16;            // n8-tiles per warp (128 rules), wc 2-way
constexpr int STEP_FLOATS = 2 * QK8 * 8 * 32 * 4;   // 6144
constexpr int STEP_BYTES  = STEP_FLOATS * 4;        // 24576

#define LOG2E 1.4426950408889634f

// ---- Device-global scratch ----
__device__ uint32_t g_Bf[NSTEP * STEP_FLOATS];  // B in mma-fragment order, tf32
__device__ float4   g_kc[Rdim];                 // -pp*sign*log2e
__device__ float4   g_cc[Rdim];                 //  pp*sign*th*log2e
__device__ float4   g_mm[Rdim];                 //  mask

__device__ __forceinline__ float ex2f(float x) {
    float y; asm("ex2.approx.f32 %0, %1;" : "=f"(y) : "f"(x)); return y;
}
__device__ __forceinline__ float rcpf(float x) {
    float y; asm("rcp.approx.f32 %0, %1;" : "=f"(y) : "f"(x)); return y;
}
__device__ __forceinline__ uint32_t to_tf32(float f) {
    uint32_t r; asm("cvt.rna.tf32.f32 %0, %1;" : "=r"(r) : "f"(f)); return r;
}

// A fragment slot (float index) for logical element (row, k).
__device__ __forceinline__ int afrag_idx(int row, int k) {
    int m = row >> 4, g = row & 7, hi = (row >> 3) & 1;
    int k8 = k >> 3, tig = k & 3, khi = (k >> 2) & 1;
    return ((m * K8 + k8) * 32 + g * 4 + tig) * 4 + (hi + 2 * khi);
}

__global__ void prep_kernel(const float* __restrict__ C,    // [R][257]
                            const float* __restrict__ pp,   // [R]
                            const float* __restrict__ th,   // [R][4]
                            const float* __restrict__ sg,   // [R][4]
                            const float* __restrict__ mk)   // [R][4]
{
    int t = blockIdx.x * blockDim.x + threadIdx.x;
    // B layout per step: [wc(2)][k8q(3)][p(8)][lane(32)][4 words]
    //   lane = n(g)*4 + tig ; words = {nt=2p,khi0},{2p,khi1},{2p+1,khi0},{2p+1,khi1}
    if (t < Rdim * K8) {
        int r  = t / K8;
        int k8 = t - r * K8;
        int chunk = r >> 8, rl = r & 255;
        int wc = rl >> 7;            // 0..1
        int nt = (rl >> 3) & 15;     // 0..15
        int nn = rl & 7;             // B operand col within n8 (= g)
        int p  = nt >> 1;
        int e  = nt & 1;
        int q = k8 / QK8, k8q = k8 - q * QK8;
        size_t stepBase = (size_t)(chunk * NQ + q) * STEP_FLOATS;
        #pragma unroll
        for (int tig = 0; tig < 4; tig++) {
            int kk0 = k8 * 8 + tig;          // khi=0
            int kk1 = k8 * 8 + 4 + tig;      // khi=1
            uint32_t v0 = (kk0 < 257) ? to_tf32(C[r * 257 + kk0]) : 0u;
            uint32_t v1 = (kk1 < 257) ? to_tf32(C[r * 257 + kk1]) : 0u;
            size_t idx = stepBase +
                (size_t)((((wc * QK8 + k8q) * 8 + p) * 32 + nn * 4 + tig) * 4 + e * 2);
            *(uint2*)&g_Bf[idx] = make_uint2(v0, v1);
        }
    }
    if (t < Rdim) {
        float s = pp[t];
        float kc[4], cc[4], mm[4];
        #pragma unroll
        for (int l = 0; l < 4; l++) {
            float sgn = sg[t * 4 + l];
            float tt  = th[t * 4 + l];
            kc[l] = -s * sgn * LOG2E;
            cc[l] =  s * sgn * tt * LOG2E;
            mm[l] = mk[t * 4 + l];
        }
        g_kc[t] = make_float4(kc[0], kc[1], kc[2], kc[3]);
        g_cc[t] = make_float4(cc[0], cc[1], cc[2], cc[3]);
        g_mm[t] = make_float4(mm[0], mm[1], mm[2], mm[3]);
    }
}

// ---- Shared memory layout (bytes) ----
constexpr int SMA  = 0;                       // A frags: 33792 u32 = 135168 B
constexpr int SMB  = 135168;                  // B double buffer: 2*24576 = 49152 B
constexpr int SMXA = 184320;                  // sXa: 64 x 132 f32 = 33792 B
constexpr int SMEM_BYTES = 218112;

__global__ __launch_bounds__(NTH, 1)
void anfis_kernel(const float* __restrict__ x,        // [B][64]
                  const float* __restrict__ aw,       // [64]
                  const int*   __restrict__ fidx,     // [R][4]
                  const int*   __restrict__ ipair,    // [P][2]
                  float*       __restrict__ out)      // [B]
{
    extern __shared__ char smem[];
    const int tid  = threadIdx.x;
    const int wid  = tid >> 5;
    const int lane = tid & 31;
    const int g    = lane >> 2;
    const int tig  = lane & 3;
    const int wr   = wid >> 1;   // 0..3 : row group (32 rows)
    const int wc   = wid & 1;    // 0..1 : rule group (128 rules)
    const int b0   = blockIdx.x * BM;

    uint32_t* sA  = (uint32_t*)smem;
    float*    sXa = (float*)(smem + SMXA);
    const uint32_t smu  = (uint32_t)__cvta_generic_to_shared(smem);
    const uint32_t smAu = smu + SMA;
    const uint32_t smBu = smu + SMB;

    // ---- Prologue: build A fragments (tf32) + sXa (f32) ----
    #pragma unroll
    for (int pass = 0; pass < 8; pass++) {
        int idx = tid + pass * NTH;     // 0..2047
        int b = idx >> 4;
        int q = idx & 15;
        int f = q * 4;
        float4 xv = *(const float4*)&x[(b0 + b) * Fdim + f];
        float4 av = __ldg((const float4*)aw + q);
        float xa[4] = {xv.x * av.x, xv.y * av.y, xv.z * av.z, xv.w * av.w};
        #pragma unroll
        for (int j = 0; j < 4; j++) {
            sA[afrag_idx(b, f + j)]      = to_tf32(xa[j]);
            sA[afrag_idx(b, 64 + f + j)] = to_tf32(xa[j] * xa[j]);
            sXa[(f + j) * 132 + b] = xa[j];
        }
    }
    __syncthreads();
    {
        int b  = tid & 127;
        int pg = tid >> 7;
        for (int pi = pg; pi < Pdim; pi += 2) {
            int2 pr = __ldg((const int2*)ipair + pi);
            float v = sXa[pr.x * 132 + b] * sXa[pr.y * 132 + b];
            sA[afrag_idx(b, 128 + pi)] = to_tf32(v);
        }
        if (pg == 0) {
            sA[afrag_idx(b, 256)] = to_tf32(1.0f);
            #pragma unroll
            for (int k = 257; k < 264; k++) sA[afrag_idx(b, k)] = 0u;
        }
    }
    __syncthreads();

    // ---- B streamer (all threads): one step = 24576 B ----
    auto issue = [&](int step) {
        const char* src = (const char*)g_Bf + (size_t)step * STEP_BYTES;
        uint32_t dst = smBu + (uint32_t)(step & 1) * STEP_BYTES;
        #pragma unroll
        for (int i = 0; i < 6; i++) {
            asm volatile("cp.async.cg.shared.global [%0], [%1], 16;"
                         :: "r"(dst + (tid + i * NTH) * 16),
                            "l"(src + (tid + i * NTH) * 16) : "memory");
        }
        asm volatile("cp.async.commit_group;" ::: "memory");
    };

    float accY[4] = {0.f, 0.f, 0.f, 0.f};
    float accS[4] = {0.f, 0.f, 0.f, 0.f};

    issue(0);

    for (int chunk = 0; chunk < NCH; chunk++) {
        float d[2][NT][4];
        #pragma unroll
        for (int mi = 0; mi < 2; mi++)
            #pragma unroll
            for (int nt = 0; nt < NT; nt++)
                #pragma unroll
                for (int rr = 0; rr < 4; rr++) d[mi][nt][rr] = 0.f;

        for (int qq = 0; qq < NQ; qq++) {
            int step = chunk * NQ + qq;
            // Data for `step` is the only pending group — drain, barrier, then
            // overlap the next step's copy with this step's MMAs.
            asm volatile("cp.async.wait_group 0;" ::: "memory");
            __syncthreads();
            if (step + 1 < NSTEP) issue(step + 1);

            uint32_t bufb = smBu + (uint32_t)(step & 1) * STEP_BYTES;

            #pragma unroll
            for (int k8q = 0; k8q < QK8; k8q++) {
                int k8 = qq * QK8 + k8q;
                uint32_t a[2][4];
                #pragma unroll
                for (int mi = 0; mi < 2; mi++) {
                    uint32_t aAddr = smAu +
                        (uint32_t)((((wr * 2 + mi) * K8 + k8) * 32 + lane) * 16);
                    asm("ld.shared.v4.b32 {%0,%1,%2,%3}, [%4];"
                        : "=r"(a[mi][0]), "=r"(a[mi][1]),
                          "=r"(a[mi][2]), "=r"(a[mi][3]) : "r"(aAddr));
                }
                uint32_t bfr[NT][2];
                #pragma unroll
                for (int p = 0; p < NT / 2; p++) {
                    uint32_t bAddr = bufb +
                        (uint32_t)((((wc * QK8 + k8q) * 8 + p) * 32 + lane) * 16);
                    asm("ld.shared.v4.b32 {%0,%1,%2,%3}, [%4];"
                        : "=r"(bfr[2 * p][0]), "=r"(bfr[2 * p][1]),
                          "=r"(bfr[2 * p + 1][0]), "=r"(bfr[2 * p + 1][1])
                        : "r"(bAddr));
                }
                #pragma unroll
                for (int mi = 0; mi < 2; mi++)
                    #pragma unroll
                    for (int nt = 0; nt < NT; nt++) {
                        asm("mma.sync.aligned.m16n8k8.row.col.f32.tf32.tf32.f32 "
                            "{%0,%1,%2,%3}, {%4,%5,%6,%7}, {%8,%9}, {%0,%1,%2,%3};"
                            : "+f"(d[mi][nt][0]), "+f"(d[mi][nt][1]),
                              "+f"(d[mi][nt][2]), "+f"(d[mi][nt][3])
                            : "r"(a[mi][0]), "r"(a[mi][1]),
                              "r"(a[mi][2]), "r"(a[mi][3]),
                              "r"(bfr[nt][0]), "r"(bfr[nt][1]));
                    }
            }
        }

        // ---- Fused epilogue: firing = 1 / prod(1 + m*exp(-z)) ----
        #pragma unroll
        for (int nt = 0; nt < NT; nt++) {
            #pragma unroll
            for (int ccc = 0; ccc < 2; ccc++) {
                int r = chunk * NCR + (wc * NT + nt) * 8 + tig * 2 + ccc;
                float4 kc = __ldg(&g_kc[r]);
                float4 cc = __ldg(&g_cc[r]);
                float4 mm = __ldg(&g_mm[r]);
                int4   id = __ldg((const int4*)fidx + r);
                const float* x0 = sXa + id.x * 132;
                const float* x1 = sXa + id.y * 132;
                const float* x2 = sXa + id.z * 132;
                const float* x3 = sXa + id.w * 132;
                #pragma unroll
                for (int mi = 0; mi < 2; mi++) {
                    #pragma unroll
                    for (int hi = 0; hi < 2; hi++) {
                        int row = wr * 32 + mi * 16 + hi * 8 + g;
                        float u0 = ex2f(fmaf(kc.x, x0[row], cc.x));
                        float u1 = ex2f(fmaf(kc.y, x1[row], cc.y));
                        float u2 = ex2f(fmaf(kc.z, x2[row], cc.z));
                        float u3 = ex2f(fmaf(kc.w, x3[row], cc.w));
                        float fac = fmaf(mm.x, u0, 1.0f) * fmaf(mm.y, u1, 1.0f)
                                  * fmaf(mm.z, u2, 1.0f) * fmaf(mm.w, u3, 1.0f);
                        float f = rcpf(fac);
                        accS[mi * 2 + hi] += f;
                        accY[mi * 2 + hi] =
                            fmaf(f, d[mi][nt][hi * 2 + ccc], accY[mi * 2 + hi]);
                    }
                }
            }
        }
    }

    // ---- Reduce: shuffle over tig (4 lanes), then smem over wc (2 warps) ----
    #pragma unroll
    for (int s = 1; s <= 2; s <<= 1) {
        #pragma unroll
        for (int i = 0; i < 4; i++) {
            accY[i] += __shfl_xor_sync(0xffffffff, accY[i], s);
            accS[i] += __shfl_xor_sync(0xffffffff, accS[i], s);
        }
    }
    __syncthreads();
    float* redY = (float*)(smem + SMB);        // [128][2]
    float* redS = redY + 256;
    if (tig == 0) {
        #pragma unroll
        for (int i = 0; i < 4; i++) {
            int row = wr * 32 + (i >> 1) * 16 + (i & 1) * 8 + g;
            redY[row * 2 + wc] = accY[i];
            redS[row * 2 + wc] = accS[i];
        }
    }
    __syncthreads();
    if (tid < BM) {
        float sy = redY[tid * 2] + redY[tid * 2 + 1];
        float ss = redS[tid * 2] + redS[tid * 2 + 1];
        out[b0 + tid] = sy / (ss + 1e-8f);
    }
}

extern "C" void kernel_launch(void* const* d_in, const int* in_sizes, int n_in,
                              void* d_out, int out_size)
{
    const float* x    = (const float*)d_in[0];   // [16384,64]
    const float* aw   = (const float*)d_in[1];   // [64]
    const float* pp   = (const float*)d_in[2];   // [1024]
    const float* th   = (const float*)d_in[3];   // [1024,4]
    const float* sg   = (const float*)d_in[4];   // [1024,4]
    const float* mk   = (const float*)d_in[5];   // [1024,4]
    const float* C    = (const float*)d_in[6];   // [1024,257]
    const int*   fid  = (const int*)  d_in[7];   // [1024,4]
    const int*   ip   = (const int*)  d_in[8];   // [128,2]
    float* out = (float*)d_out;

    cudaFuncSetAttribute(anfis_kernel,
                         cudaFuncAttributeMaxDynamicSharedMemorySize,
                         SMEM_BYTES);

    prep_kernel<<<132, 256>>>(C, pp, th, sg, mk);
    anfis_kernel<<<16384 / BM, NTH, SMEM_BYTES>>>(x, aw, fid, ip, out);
}